// round 1
// baseline (speedup 1.0000x reference)
#include <cuda_runtime.h>

#define BB 64
#define HH 1024
#define TT 1024
#define VV 32000

// ---------------- scratch (no allocs allowed) ----------------
__device__ float g_emb[BB * HH];
__device__ float g_gx[BB * 3 * HH];
__device__ float g_gh[BB * 3 * HH];
__device__ float g_concat_in[BB * 2 * HH];
__device__ float g_concat_out[BB * HH];
__device__ float g_scores[BB * TT];
__device__ float g_cpart[BB * VV];   // max partial buffer (2,048,000 floats)

// ---------------- embedding gather ----------------
__global__ void k_embed(const int* __restrict__ seq, const float* __restrict__ table) {
    int i = blockIdx.x * 256 + threadIdx.x;       // B*H = 65536
    int b = i >> 10;
    int h = i & 1023;
    g_emb[i] = table[(long)seq[b] * HH + h];
}

// ---------------- generic GEMM: Cpart[split][b][n] = X[64,K] @ W[N,K]^T ----------------
// grid: (N/64, ksplit), block 256. kpb = K / ksplit, must be multiple of 16.
__global__ void k_gemm(const float* __restrict__ X, const float* __restrict__ W,
                       float* __restrict__ Cp, int N, int K, int kpb) {
    __shared__ float Xs[16][68];
    __shared__ float Ws[16][68];
    int t  = threadIdx.x;
    int n0 = blockIdx.x * 64;
    int kb = blockIdx.y * kpb;
    float acc[4][4] = {};
    int tb = (t & 15) * 4;     // b-base
    int tn = (t >> 4) * 4;     // n-base within tile

    for (int k0 = kb; k0 < kb + kpb; k0 += 16) {
#pragma unroll
        for (int i = 0; i < 4; i++) {
            int e  = t + i * 256;
            int kk = e & 15;
            int r  = e >> 4;
            Xs[kk][r] = X[r * K + k0 + kk];
            Ws[kk][r] = W[(n0 + r) * K + k0 + kk];
        }
        __syncthreads();
#pragma unroll
        for (int kk = 0; kk < 16; kk++) {
            float4 xv = *(const float4*)&Xs[kk][tb];
            float4 wv = *(const float4*)&Ws[kk][tn];
            acc[0][0] += xv.x * wv.x; acc[0][1] += xv.x * wv.y; acc[0][2] += xv.x * wv.z; acc[0][3] += xv.x * wv.w;
            acc[1][0] += xv.y * wv.x; acc[1][1] += xv.y * wv.y; acc[1][2] += xv.y * wv.z; acc[1][3] += xv.y * wv.w;
            acc[2][0] += xv.z * wv.x; acc[2][1] += xv.z * wv.y; acc[2][2] += xv.z * wv.z; acc[2][3] += xv.z * wv.w;
            acc[3][0] += xv.w * wv.x; acc[3][1] += xv.w * wv.y; acc[3][2] += xv.w * wv.z; acc[3][3] += xv.w * wv.w;
        }
        __syncthreads();
    }
    float* outp = Cp + (size_t)blockIdx.y * (BB * N);
#pragma unroll
    for (int i = 0; i < 4; i++) {
        float4 v = make_float4(acc[i][0], acc[i][1], acc[i][2], acc[i][3]);
        *(float4*)&outp[(tb + i) * N + n0 + tn] = v;
    }
}

// ---------------- combine splits + bias + optional tanh ----------------
__global__ void k_combine(const float* __restrict__ Cp, const float* __restrict__ bias,
                          float* __restrict__ C, int N, int ksplit, int act) {
    int i = blockIdx.x * 256 + threadIdx.x;
    float v = 0.f;
    for (int s = 0; s < ksplit; s++) v += Cp[(size_t)s * (BB * N) + i];
    v += bias[i % N];
    if (act) v = tanhf(v);
    C[i] = v;
}

// ---------------- GRU gates ----------------
__global__ void k_gate(const float* __restrict__ last_hidden, float* __restrict__ out_hidden) {
    int i = blockIdx.x * 256 + threadIdx.x;   // B*H
    int b = i >> 10;
    int h = i & 1023;
    const float* gx = g_gx + b * 3 * HH;
    const float* gh = g_gh + b * 3 * HH;
    float r = 1.f / (1.f + expf(-(gx[h] + gh[h])));
    float z = 1.f / (1.f + expf(-(gx[HH + h] + gh[HH + h])));
    float n = tanhf(gx[2 * HH + h] + r * gh[2 * HH + h]);
    float hp = last_hidden[i];
    float hn = (1.f - z) * n + z * hp;
    out_hidden[i] = hn;
    g_concat_in[b * 2 * HH + h] = hn;
}

// ---------------- attention scores: scores[b,t] = h_b . e[t,b,:] ----------------
__global__ void k_scores(const float* __restrict__ enc, const float* __restrict__ hnew) {
    int b = blockIdx.y;
    int t = blockIdx.x * 8 + (threadIdx.x >> 5);
    int lane = threadIdx.x & 31;
    const float* e = enc + ((size_t)t * BB + b) * HH;
    const float* h = hnew + b * HH;
    float acc = 0.f;
#pragma unroll 8
    for (int i = lane; i < HH; i += 32) acc += e[i] * h[i];
#pragma unroll
    for (int o = 16; o; o >>= 1) acc += __shfl_xor_sync(0xffffffffu, acc, o);
    if (lane == 0) g_scores[b * TT + t] = acc;
}

// ---------------- softmax over t, writes attn to out region ----------------
__global__ void k_softmax(float* __restrict__ attn_out) {
    int b = blockIdx.x;
    int tid = threadIdx.x;
    __shared__ float red[256];
    const float* s = g_scores + b * TT;
    float v[4];
    float m = -1e30f;
#pragma unroll
    for (int j = 0; j < 4; j++) { v[j] = s[tid + j * 256]; m = fmaxf(m, v[j]); }
    red[tid] = m; __syncthreads();
    for (int o = 128; o; o >>= 1) { if (tid < o) red[tid] = fmaxf(red[tid], red[tid + o]); __syncthreads(); }
    m = red[0]; __syncthreads();
    float sum = 0.f;
#pragma unroll
    for (int j = 0; j < 4; j++) { v[j] = expf(v[j] - m); sum += v[j]; }
    red[tid] = sum; __syncthreads();
    for (int o = 128; o; o >>= 1) { if (tid < o) red[tid] += red[tid + o]; __syncthreads(); }
    float inv = 1.f / red[0];
#pragma unroll
    for (int j = 0; j < 4; j++) attn_out[b * TT + tid + j * 256] = v[j] * inv;
}

// ---------------- context[b,h] = sum_t attn[b,t] * e[t,b,h] ----------------
__global__ void k_context(const float* __restrict__ enc, const float* __restrict__ attn) {
    int b = blockIdx.x;
    int h = blockIdx.y * 256 + threadIdx.x;
    __shared__ float as[TT];
#pragma unroll
    for (int j = 0; j < 4; j++) as[threadIdx.x + j * 256] = attn[b * TT + threadIdx.x + j * 256];
    __syncthreads();
    const float* e = enc + b * HH + h;
    float a0 = 0.f, a1 = 0.f, a2 = 0.f, a3 = 0.f;
    for (int t = 0; t < TT; t += 4) {
        a0 += as[t + 0] * e[(size_t)(t + 0) * BB * HH];
        a1 += as[t + 1] * e[(size_t)(t + 1) * BB * HH];
        a2 += as[t + 2] * e[(size_t)(t + 2) * BB * HH];
        a3 += as[t + 3] * e[(size_t)(t + 3) * BB * HH];
    }
    g_concat_in[b * 2 * HH + HH + h] = (a0 + a1) + (a2 + a3);
}

// ---------------- launcher ----------------
extern "C" void kernel_launch(void* const* d_in, const int* in_sizes, int n_in,
                              void* d_out, int out_size) {
    const int*   seq         = (const int*)d_in[0];
    const float* last_hidden = (const float*)d_in[1];
    const float* enc         = (const float*)d_in[2];
    const float* emb_table   = (const float*)d_in[3];
    const float* w_ih        = (const float*)d_in[4];
    const float* w_hh        = (const float*)d_in[5];
    const float* b_ih        = (const float*)d_in[6];
    const float* b_hh        = (const float*)d_in[7];
    const float* concat_W    = (const float*)d_in[8];
    const float* concat_b    = (const float*)d_in[9];
    const float* out_W       = (const float*)d_in[10];
    const float* out_b       = (const float*)d_in[11];

    float* out        = (float*)d_out;             // [B, V]
    float* out_hidden = out + BB * VV;             // [1, B, H]
    float* out_attn   = out + BB * VV + BB * HH;   // [B, 1, T]

    float *p_emb, *p_gx, *p_gh, *p_cin, *p_cout, *p_cp;
    cudaGetSymbolAddress((void**)&p_emb,  g_emb);
    cudaGetSymbolAddress((void**)&p_gx,   g_gx);
    cudaGetSymbolAddress((void**)&p_gh,   g_gh);
    cudaGetSymbolAddress((void**)&p_cin,  g_concat_in);
    cudaGetSymbolAddress((void**)&p_cout, g_concat_out);
    cudaGetSymbolAddress((void**)&p_cp,   g_cpart);

    // 1. embedding
    k_embed<<<256, 256>>>(seq, emb_table);
    // 2. gx = emb @ w_ih^T + b_ih   (N=3072, K=1024, ksplit=4)
    k_gemm<<<dim3(48, 4), 256>>>(p_emb, w_ih, p_cp, 3 * HH, HH, 256);
    k_combine<<<768, 256>>>(p_cp, b_ih, p_gx, 3 * HH, 4, 0);
    // 3. gh = h @ w_hh^T + b_hh
    k_gemm<<<dim3(48, 4), 256>>>(last_hidden, w_hh, p_cp, 3 * HH, HH, 256);
    k_combine<<<768, 256>>>(p_cp, b_hh, p_gh, 3 * HH, 4, 0);
    // 4. GRU gates -> h_new (to out_hidden and concat_in[:, :H])
    k_gate<<<256, 256>>>(last_hidden, out_hidden);
    // 5. attention scores
    k_scores<<<dim3(128, 64), 256>>>(enc, out_hidden);
    // 6. softmax -> out_attn
    k_softmax<<<64, 256>>>(out_attn);
    // 7. context -> concat_in[:, H:]
    k_context<<<dim3(64, 4), 256>>>(enc, out_attn);
    // 8. concat_output = tanh(concat_in @ concat_W^T + concat_b)  (N=1024, K=2048, ksplit=8)
    k_gemm<<<dim3(16, 8), 256>>>(p_cin, concat_W, p_cp, HH, 2 * HH, 256);
    k_combine<<<256, 256>>>(p_cp, concat_b, p_cout, HH, 8, 1);
    // 9. output = concat_out @ out_W^T + out_b  (N=32000, K=1024)
    k_gemm<<<dim3(500, 1), 256>>>(p_cout, out_W, p_cp, VV, HH, 1024);
    k_combine<<<8000, 256>>>(p_cp, out_b, out, VV, 1, 0);
}